// round 6
// baseline (speedup 1.0000x reference)
#include <cuda_runtime.h>
#include <cuda_fp16.h>
#include <cstdint>

#define BB   32
#define SS   512
#define CC   512
#define LLR  2048
#define NPOS (BB*SS)
#define WELEM (512*1536)

static const long long OUT_EXP = 33554432LL;  // 32*2048*512
static const long long OUT_LD  = 16384LL;     // 32*512
static const long long OUT_MEL = 65536LL;     // 32*2048

// ---------------- device-global scratch ----------------
__device__ __half g_Xh[(size_t)NPOS*CC];
__device__ __half g_Xl[(size_t)NPOS*CC];
__device__ __half g_Hh[(size_t)NPOS*CC];
__device__ __half g_Hl[(size_t)NPOS*CC];
__device__ __half g_W1h[WELEM];
__device__ __half g_W2h[WELEM];
__device__ float g_Y[(size_t)NPOS*CC];
__device__ float g_dummy[NPOS];

// ---------------- helpers ----------------
__device__ __forceinline__ uint32_t smem_u32(const void* p){
    uint32_t a;
    asm("{ .reg .u64 t; cvta.to.shared.u64 t, %1; cvt.u32.u64 %0, t; }" : "=r"(a) : "l"(p));
    return a;
}
#define SWZ(x) ((uint32_t)(x) ^ ((((uint32_t)(x))>>3)&0x70))

__device__ __forceinline__ void cpa16(uint32_t dst, const void* src, int srcsize){
    asm volatile("cp.async.cg.shared.global [%0], [%1], 16, %2;"
                 :: "r"(dst), "l"(src), "r"(srcsize));
}
#define CP_COMMIT()  asm volatile("cp.async.commit_group;" ::: "memory")
#define CP_WAIT1()   asm volatile("cp.async.wait_group 1;" ::: "memory")
#define CP_WAIT0()   asm volatile("cp.async.wait_group 0;" ::: "memory")

__device__ __forceinline__ void ldsm4(uint32_t& r0, uint32_t& r1, uint32_t& r2, uint32_t& r3,
                                      uint32_t addr){
    asm volatile("ldmatrix.sync.aligned.m8n8.x4.shared.b16 {%0,%1,%2,%3}, [%4];"
                 : "=r"(r0), "=r"(r1), "=r"(r2), "=r"(r3) : "r"(addr));
}
// fp32-accumulate fp16 MMA (hi term)
__device__ __forceinline__ void mma16816(float* d, const uint32_t* a, uint32_t b0, uint32_t b1){
    asm volatile("mma.sync.aligned.m16n8k16.row.col.f32.f16.f16.f32 "
                 "{%0,%1,%2,%3}, {%4,%5,%6,%7}, {%8,%9}, {%0,%1,%2,%3};"
                 : "+f"(d[0]), "+f"(d[1]), "+f"(d[2]), "+f"(d[3])
                 : "r"(a[0]), "r"(a[1]), "r"(a[2]), "r"(a[3]), "r"(b0), "r"(b1));
}
// fp16-accumulate fp16 MMA (low term) — potentially 2x rate
__device__ __forceinline__ void mma16816h(uint32_t* d, const uint32_t* a, uint32_t b0, uint32_t b1){
    asm volatile("mma.sync.aligned.m16n8k16.row.col.f16.f16.f16.f16 "
                 "{%0,%1}, {%2,%3,%4,%5}, {%6,%7}, {%0,%1};"
                 : "+r"(d[0]), "+r"(d[1])
                 : "r"(a[0]), "r"(a[1]), "r"(a[2]), "r"(a[3]), "r"(b0), "r"(b1));
}

__device__ __forceinline__ void split_h(float v, __half& h, __half& l){
    h = __float2half_rn(v);
    l = __float2half_rn(v - __half2float(h));
}

// ---------------- fused prep: X split + W transpose/convert ----------------
#define NXBLK (NPOS*CC/256)          // 32768
#define NWBLK (2*WELEM/256)          // 6144
__global__ void k_prep(const float* __restrict__ x,
                       const float* __restrict__ w1, const float* __restrict__ w2)
{
    if (blockIdx.x < NXBLK) {
        int i = blockIdx.x * 256 + threadIdx.x;
        float v = x[i];
        __half h, l; split_h(v, h, l);
        g_Xh[i] = h; g_Xl[i] = l;
    } else {
        int i = (blockIdx.x - NXBLK) * 256 + threadIdx.x;   // 0..2*WELEM-1
        int layer = i >= WELEM;
        int j = layer ? i - WELEM : i;
        int co = j / 1536;
        int r  = j - co * 1536;
        int k  = r >> 9;
        int ci = r & 511;
        const float* w = layer ? w2 : w1;
        __half h = __float2half_rn(w[(co * 512 + ci) * 3 + k]);
        if (layer) g_W2h[j] = h; else g_W1h[j] = h;
    }
}

// ---------------- mma.sync conv GEMM (hi: fp32-acc, lo: fp16-acc) ----------------
// C[16384,512] = A[16384,1536] * W^T.  A[p][shift*512+ci] = X[p+shift-1][ci].
// CTA 128x128, 8 warps (4M x 2N) of 32x64. K chunks of 64, SW128 128B rows.
// 2-stage cp.async pipeline, 48KB/stage. 1 CTA/SM (regs); perf is occ-invariant.
#define NCHUNK 24
#define ST_AH 0
#define ST_AL (16*1024)
#define ST_WH (32*1024)
#define STAGE_BYTES (48*1024)
#define MMA_SMEM_TOTAL (2*STAGE_BYTES)   // 98304

struct MPtr { const __half *ah, *al, *wh; };

__global__ void __launch_bounds__(256) k_mma(int layer)
{
    extern __shared__ __align__(1024) char smem[];
    uint32_t sb = smem_u32(smem);
    const int tid  = threadIdx.x;
    const int wid  = tid >> 5;
    const int lane = tid & 31;

    const int p0  = blockIdx.x * 128;
    const int co0 = blockIdx.y * 128;
    const int batch_base = p0 & ~511;
    const int srow0      = p0 & 511;

    MPtr P;
    if (layer) { P.ah = g_Hh; P.al = g_Hl; P.wh = g_W2h; }
    else       { P.ah = g_Xh; P.al = g_Xl; P.wh = g_W1h; }

    // ---- precomputed load slots (12 cp.async per thread per chunk) ----
    const __half* aptr0[8]; uint32_t adst[8]; int arow[8];
#pragma unroll
    for (int it = 0; it < 8; it++) {
        int u = tid + it * 256;
        int split = u >> 10;
        int row   = (u >> 3) & 127;
        int cu    = u & 7;
        arow[it] = srow0 + row - 1;
        const __half* base = split ? P.al : P.ah;
        aptr0[it] = base + (size_t)batch_base * CC + (ptrdiff_t)arow[it] * CC + cu * 8;
        adst[it]  = (split ? ST_AL : ST_AH) + SWZ(row * 128 + cu * 16);
    }
    const __half* wptr0[4]; uint32_t wdst[4];
#pragma unroll
    for (int it = 0; it < 4; it++) {
        int u = tid + it * 256;
        int row = u >> 3;
        int cu  = u & 7;
        wptr0[it] = P.wh + (size_t)(co0 + row) * 1536 + cu * 8;
        wdst[it]  = ST_WH + SWZ(row * 128 + cu * 16);
    }

#define LOAD_CHUNK(c_, stagebase_) do {                                      \
    const int shift_ = (c_) >> 3;                                            \
    const int koff_  = shift_ * 512 + ((c_) & 7) * 64;                       \
    _Pragma("unroll")                                                        \
    for (int it = 0; it < 8; it++) {                                         \
        bool v_ = (unsigned)(arow[it] + shift_) < 512u;                      \
        cpa16((stagebase_) + adst[it], v_ ? (aptr0[it] + koff_) : P.ah,      \
              v_ ? 16 : 0);                                                  \
    }                                                                        \
    _Pragma("unroll")                                                        \
    for (int it = 0; it < 4; it++)                                           \
        cpa16((stagebase_) + wdst[it], wptr0[it] + koff_, 16);               \
    CP_COMMIT();                                                             \
} while (0)

    float acc[2][8][4];
    uint32_t acch[2][8][2];
#pragma unroll
    for (int i = 0; i < 2; i++)
#pragma unroll
        for (int j = 0; j < 8; j++) {
#pragma unroll
            for (int k = 0; k < 4; k++) acc[i][j][k] = 0.f;
            acch[i][j][0] = 0u; acch[i][j][1] = 0u;
        }

    LOAD_CHUNK(0, sb);
    LOAD_CHUNK(1, sb + STAGE_BYTES);

    // ---- frag address constants ----
    const int m0w  = (wid & 3) * 32;
    const int n0w  = (wid >> 2) * 64;
    const int lrow = lane & 15;
    const int lub  = (lane >> 4) * 16;
    uint32_t aoffH[2], aoffL[2], xrA[2];
#pragma unroll
    for (int mt = 0; mt < 2; mt++) {
        int row = m0w + mt * 16 + lrow;
        aoffH[mt] = ST_AH + row * 128;
        aoffL[mt] = ST_AL + row * 128;
        xrA[mt]   = (row & 7) << 4;
    }
    uint32_t boff[4], xrB[4];
#pragma unroll
    for (int np = 0; np < 4; np++) {
        int row = n0w + np * 16 + lrow;
        boff[np] = ST_WH + row * 128;
        xrB[np]  = (row & 7) << 4;
    }

#pragma unroll 1
    for (int c = 0; c < NCHUNK; c++) {
        uint32_t stage = sb + (uint32_t)(c & 1) * STAGE_BYTES;
        if (c + 1 < NCHUNK) { CP_WAIT1(); } else { CP_WAIT0(); }
        __syncthreads();

#pragma unroll
        for (int ks = 0; ks < 4; ks++) {
            const uint32_t kb = (uint32_t)(ks * 32) + lub;

            uint32_t ahf[2][4], alf[2][4], bhf[4][4];
#pragma unroll
            for (int mt = 0; mt < 2; mt++) {
                ldsm4(ahf[mt][0], ahf[mt][1], ahf[mt][2], ahf[mt][3],
                      stage + aoffH[mt] + (kb ^ xrA[mt]));
                ldsm4(alf[mt][0], alf[mt][1], alf[mt][2], alf[mt][3],
                      stage + aoffL[mt] + (kb ^ xrA[mt]));
            }
#pragma unroll
            for (int np = 0; np < 4; np++)
                ldsm4(bhf[np][0], bhf[np][1], bhf[np][2], bhf[np][3],
                      stage + boff[np] + (kb ^ xrB[np]));

#pragma unroll
            for (int mt = 0; mt < 2; mt++)
#pragma unroll
                for (int np = 0; np < 4; np++) {
                    mma16816(acc[mt][2*np],    ahf[mt], bhf[np][0], bhf[np][2]);
                    mma16816(acc[mt][2*np+1],  ahf[mt], bhf[np][1], bhf[np][3]);
                    mma16816h(acch[mt][2*np],   alf[mt], bhf[np][0], bhf[np][2]);
                    mma16816h(acch[mt][2*np+1], alf[mt], bhf[np][1], bhf[np][3]);
                }
        }
        __syncthreads();
        if (c + 2 < NCHUNK)
            LOAD_CHUNK(c + 2, stage);
    }

    // ---- epilogue: merge fp16 low-term accumulators, store fp32 ----
    const int gr = lane >> 2;
    const int gc = (lane & 3) * 2;
#pragma unroll
    for (int mt = 0; mt < 2; mt++) {
        int row = p0 + m0w + mt * 16 + gr;
#pragma unroll
        for (int nt = 0; nt < 8; nt++) {
            __half2 h01 = *reinterpret_cast<__half2*>(&acch[mt][nt][0]);
            __half2 h23 = *reinterpret_cast<__half2*>(&acch[mt][nt][1]);
            float v0 = acc[mt][nt][0] + __half2float(h01.x);
            float v1 = acc[mt][nt][1] + __half2float(h01.y);
            float v2 = acc[mt][nt][2] + __half2float(h23.x);
            float v3 = acc[mt][nt][3] + __half2float(h23.y);
            int col = co0 + n0w + nt * 8 + gc;
            *(float2*)(g_Y + (size_t)row * CC + col)       = make_float2(v0, v1);
            *(float2*)(g_Y + (size_t)(row + 8) * CC + col) = make_float2(v2, v3);
        }
    }
}

// ---------------- bias + relu + LayerNorm (+ optional linear head) ----------------
template<int MODE>
__global__ void k_ln(const float* __restrict__ bias, const float* __restrict__ lng,
                     const float* __restrict__ lnb, const float* __restrict__ lw,
                     const float* __restrict__ lbias, float* __restrict__ outp)
{
    __shared__ float s1[4], s2[4], sd[4];
    const int row = blockIdx.x, tid = threadIdx.x;
    const int wid = tid >> 5, lane = tid & 31;

    float4 v  = ((const float4*)(g_Y + (size_t)row * CC))[tid];
    float4 bb = ((const float4*)bias)[tid];
    float e0 = fmaxf(v.x + bb.x, 0.f);
    float e1 = fmaxf(v.y + bb.y, 0.f);
    float e2 = fmaxf(v.z + bb.z, 0.f);
    float e3 = fmaxf(v.w + bb.w, 0.f);

    float s = e0 + e1 + e2 + e3;
    float q = e0*e0 + e1*e1 + e2*e2 + e3*e3;
#pragma unroll
    for (int o = 16; o > 0; o >>= 1) {
        s += __shfl_xor_sync(0xffffffffu, s, o);
        q += __shfl_xor_sync(0xffffffffu, q, o);
    }
    if (lane == 0) { s1[wid] = s; s2[wid] = q; }
    __syncthreads();
    float ts = s1[0] + s1[1] + s1[2] + s1[3];
    float tq = s2[0] + s2[1] + s2[2] + s2[3];
    float mu = ts * (1.f / 512.f);
    float rs = rsqrtf(tq * (1.f / 512.f) - mu * mu + 1e-5f);

    float4 gg = ((const float4*)lng)[tid];
    float4 bn = ((const float4*)lnb)[tid];
    float o0 = (e0 - mu) * rs * gg.x + bn.x;
    float o1 = (e1 - mu) * rs * gg.y + bn.y;
    float o2 = (e2 - mu) * rs * gg.z + bn.z;
    float o3 = (e3 - mu) * rs * gg.w + bn.w;

    if (MODE == 0) {
        __half h0,l0,h1,l1,h2,l2,h3,l3;
        split_h(o0,h0,l0); split_h(o1,h1,l1);
        split_h(o2,h2,l2); split_h(o3,h3,l3);
        uint32_t hw0 = ((uint32_t)*(unsigned short*)&h1 << 16) | *(unsigned short*)&h0;
        uint32_t hw1 = ((uint32_t)*(unsigned short*)&h3 << 16) | *(unsigned short*)&h2;
        uint32_t lw0 = ((uint32_t)*(unsigned short*)&l1 << 16) | *(unsigned short*)&l0;
        uint32_t lw1 = ((uint32_t)*(unsigned short*)&l3 << 16) | *(unsigned short*)&l2;
        ((uint2*)(g_Hh + (size_t)row * CC))[tid] = make_uint2(hw0, hw1);
        ((uint2*)(g_Hl + (size_t)row * CC))[tid] = make_uint2(lw0, lw1);
    } else {
        float4 lv = ((const float4*)lw)[tid];
        float d = o0 * lv.x + o1 * lv.y + o2 * lv.z + o3 * lv.w;
#pragma unroll
        for (int o = 16; o > 0; o >>= 1)
            d += __shfl_xor_sync(0xffffffffu, d, o);
        if (lane == 0) sd[wid] = d;
        __syncthreads();
        if (tid == 0) {
            float* dst = outp ? outp : g_dummy;
            dst[row] = sd[0] + sd[1] + sd[2] + sd[3] + lbias[0];
        }
    }
}

// ---------------- length regulator (fused cumsum + expand) ----------------
__global__ void k_expand(const float* __restrict__ x, const int* __restrict__ dur,
                         float* __restrict__ out)
{
    __shared__ int sc[512];
    __shared__ int ps[256];
    const int b = blockIdx.y, tid = threadIdx.x;

    // local inclusive scan of this batch's 512 durations
    int d0 = dur[b * SS + 2 * tid];
    int d1 = dur[b * SS + 2 * tid + 1];
    ps[tid] = d0 + d1;
    __syncthreads();
#pragma unroll
    for (int off = 1; off < 256; off <<= 1) {
        int v = (tid >= off) ? ps[tid - off] : 0;
        __syncthreads();
        ps[tid] += v;
        __syncthreads();
    }
    int excl = ps[tid] - d0 - d1;
    sc[2 * tid]     = excl + d0;
    sc[2 * tid + 1] = excl + d0 + d1;
    __syncthreads();

    const int w    = tid >> 5;
    const int lane = tid & 31;
    const int t    = blockIdx.x * 8 + w;
    const int total = sc[511];
    const bool valid = t < total;

    int lo = 0, hi = 512;
    while (lo < hi) {
        int mid = (lo + hi) >> 1;
        if (sc[mid] <= t) lo = mid + 1; else hi = mid;
    }
    int idx = lo < 511 ? lo : 511;

    const float4* src = (const float4*)(x + ((size_t)b * SS + idx) * CC);
    float4*       dst = (float4*)(out + ((size_t)b * LLR + t) * CC);
    float4 z = make_float4(0.f, 0.f, 0.f, 0.f);
#pragma unroll
    for (int i = 0; i < 4; i++) {
        float4 v = valid ? src[lane + i * 32] : z;
        dst[lane + i * 32] = v;
    }
}

__global__ void k_zero(float* __restrict__ p, int n)
{
    int i = blockIdx.x * blockDim.x + threadIdx.x;
    if (i < n) p[i] = 0.f;
}

// ---------------------------------------------------------------------------
extern "C" void kernel_launch(void* const* d_in, const int* in_sizes, int n_in,
                              void* d_out, int out_size)
{
    (void)in_sizes; (void)n_in;
    const float* x   = (const float*)d_in[0];
    const int*   dur = (const int*)d_in[6];
    const float* w1  = (const float*)d_in[7];
    const float* b1  = (const float*)d_in[8];
    const float* g1  = (const float*)d_in[9];
    const float* lb1 = (const float*)d_in[10];
    const float* w2  = (const float*)d_in[11];
    const float* b2  = (const float*)d_in[12];
    const float* g2  = (const float*)d_in[13];
    const float* lb2 = (const float*)d_in[14];
    const float* lw  = (const float*)d_in[15];
    const float* lb  = (const float*)d_in[16];
    float* out = (float*)d_out;

    const bool has_ld  = (long long)out_size >= OUT_EXP + OUT_LD;
    const bool has_mel = (long long)out_size >= OUT_EXP + OUT_LD + OUT_MEL;

    cudaFuncSetAttribute(k_mma, cudaFuncAttributeMaxDynamicSharedMemorySize, MMA_SMEM_TOTAL);

    // order: expand(1), zero(2), prep(3), mma0(4), ln0(5), mma1(6) — keeps k_mma in
    // the ncu -s 5 -c 1 capture window
    k_expand<<<dim3(LLR / 8, BB), 256>>>(x, dur, out);
    if (has_mel)
        k_zero<<<(int)((OUT_MEL + 255) / 256), 256>>>(out + OUT_EXP + OUT_LD, (int)OUT_MEL);
    k_prep<<<NXBLK + NWBLK, 256>>>(x, w1, w2);

    k_mma<<<dim3(128, 4), 256, MMA_SMEM_TOTAL>>>(0);
    k_ln<0><<<NPOS, 128>>>(b1, g1, lb1, nullptr, nullptr, nullptr);

    k_mma<<<dim3(128, 4), 256, MMA_SMEM_TOTAL>>>(1);
    k_ln<1><<<NPOS, 128>>>(b2, g2, lb2, lw, lb, has_ld ? (out + OUT_EXP) : nullptr);
}

// round 8
// speedup vs baseline: 1.7256x; 1.7256x over previous
#include <cuda_runtime.h>
#include <cuda_fp16.h>
#include <cstdint>

#define BB   32
#define SS   512
#define CC   512
#define LLR  2048
#define NPOS (BB*SS)
#define WELEM (512*1536)

static const long long OUT_EXP = 33554432LL;  // 32*2048*512
static const long long OUT_LD  = 16384LL;     // 32*512
static const long long OUT_MEL = 65536LL;     // 32*2048

// ---------------- device-global scratch ----------------
__device__ __half g_Xh[(size_t)NPOS*CC];
__device__ __half g_Hh[(size_t)NPOS*CC];
__device__ __half g_W1h[WELEM];
__device__ __half g_W2h[WELEM];
__device__ float g_Y[(size_t)NPOS*CC];
__device__ float g_dummy[NPOS];

// ---------------- helpers ----------------
__device__ __forceinline__ uint32_t smem_u32(const void* p){
    uint32_t a;
    asm("{ .reg .u64 t; cvta.to.shared.u64 t, %1; cvt.u32.u64 %0, t; }" : "=r"(a) : "l"(p));
    return a;
}
#define SWZ(x) ((uint32_t)(x) ^ ((((uint32_t)(x))>>3)&0x70))

__device__ __forceinline__ void cpa16(uint32_t dst, const void* src, int srcsize){
    asm volatile("cp.async.cg.shared.global [%0], [%1], 16, %2;"
                 :: "r"(dst), "l"(src), "r"(srcsize));
}
#define CP_COMMIT()  asm volatile("cp.async.commit_group;" ::: "memory")
#define CP_WAIT1()   asm volatile("cp.async.wait_group 1;" ::: "memory")
#define CP_WAIT0()   asm volatile("cp.async.wait_group 0;" ::: "memory")

__device__ __forceinline__ void ldsm4(uint32_t& r0, uint32_t& r1, uint32_t& r2, uint32_t& r3,
                                      uint32_t addr){
    asm volatile("ldmatrix.sync.aligned.m8n8.x4.shared.b16 {%0,%1,%2,%3}, [%4];"
                 : "=r"(r0), "=r"(r1), "=r"(r2), "=r"(r3) : "r"(addr));
}
__device__ __forceinline__ void mma16816(float* d, const uint32_t* a, uint32_t b0, uint32_t b1){
    asm volatile("mma.sync.aligned.m16n8k16.row.col.f32.f16.f16.f32 "
                 "{%0,%1,%2,%3}, {%4,%5,%6,%7}, {%8,%9}, {%0,%1,%2,%3};"
                 : "+f"(d[0]), "+f"(d[1]), "+f"(d[2]), "+f"(d[3])
                 : "r"(a[0]), "r"(a[1]), "r"(a[2]), "r"(a[3]), "r"(b0), "r"(b1));
}

// ---------------- prep: X -> fp16, W -> transposed fp16 ----------------
#define NXBLK 2048                   // X: 2048 blocks x 256 thr x 16 elems
#define NWBLK (2*WELEM/256)          // 6144
__global__ void k_prep(const float* __restrict__ x,
                       const float* __restrict__ w1, const float* __restrict__ w2)
{
    if (blockIdx.x < NXBLK) {
        int base = (blockIdx.x * 256 + threadIdx.x) * 16;
#pragma unroll
        for (int q = 0; q < 4; q++) {
            float4 v = *(const float4*)(x + base + q * 4);
            __half2 a = __floats2half2_rn(v.x, v.y);
            __half2 b = __floats2half2_rn(v.z, v.w);
            *(__half2*)(g_Xh + base + q * 4)     = a;
            *(__half2*)(g_Xh + base + q * 4 + 2) = b;
        }
    } else {
        int i = (blockIdx.x - NXBLK) * 256 + threadIdx.x;   // 0..2*WELEM-1
        int layer = i >= WELEM;
        int j = layer ? i - WELEM : i;
        int co = j / 1536;
        int r  = j - co * 1536;
        int k  = r >> 9;
        int ci = r & 511;
        const float* w = layer ? w2 : w1;
        __half h = __float2half_rn(w[(co * 512 + ci) * 3 + k]);
        if (layer) g_W2h[j] = h; else g_W1h[j] = h;
    }
}

// ---------------- single-term fp16 conv GEMM (+ fused length regulator) ----------------
// C[16384,512] = A[16384,1536] * W^T.  A[p][shift*512+ci] = X[p+shift-1][ci].
// CTA 128x128 (blockIdx.y<4 = column tile), 8 warps (4M x 2N) of 32x64.
// K chunks of 64, SW128 128B rows, 2-stage cp.async, 32KB/stage -> 2 CTAs/SM.
// blockIdx.y==4 (layer 0 only): length-regulator CTAs (memory-bound, overlap).
#define NCHUNK 24
#define ST_AH 0
#define ST_WH (16*1024)
#define STAGE_BYTES (32*1024)
#define MMA_SMEM_TOTAL (2*STAGE_BYTES)   // 65536

__global__ void __launch_bounds__(256, 2) k_mma(int layer,
                                                const float* __restrict__ x,
                                                const int* __restrict__ dur,
                                                float* __restrict__ out,
                                                float* __restrict__ mel)
{
    extern __shared__ __align__(1024) char smem[];
    const int tid  = threadIdx.x;

    // ================= length-regulator slice (layer 0, y==4) =================
    if (blockIdx.y == 4) {
        int* sc = (int*)smem;        // 512 ints
        int* ps = sc + 512;          // 256 ints
        const int bx = blockIdx.x;         // 0..127
        const int b  = bx >> 2;            // batch
        const int qu = bx & 3;             // quarter of the 2048 frames

        // zero mel slice: 128 blocks x 512 floats = 65536
        if (mel) {
            mel[bx * 512 + tid] = 0.f;
            mel[bx * 512 + 256 + tid] = 0.f;
        }

        int d0 = dur[b * SS + 2 * tid];
        int d1 = dur[b * SS + 2 * tid + 1];
        ps[tid] = d0 + d1;
        __syncthreads();
#pragma unroll
        for (int off = 1; off < 256; off <<= 1) {
            int v = (tid >= off) ? ps[tid - off] : 0;
            __syncthreads();
            ps[tid] += v;
            __syncthreads();
        }
        int excl = ps[tid] - d0 - d1;
        sc[2 * tid]     = excl + d0;
        sc[2 * tid + 1] = excl + d0 + d1;
        __syncthreads();

        const int w    = tid >> 5;
        const int lane = tid & 31;
        const int total = sc[511];
        const float4 z = make_float4(0.f, 0.f, 0.f, 0.f);
#pragma unroll 1
        for (int f = 0; f < 64; f++) {
            const int t = qu * 512 + w * 64 + f;
            const bool valid = t < total;
            int lo = 0, hi = 512;
            while (lo < hi) {
                int mid = (lo + hi) >> 1;
                if (sc[mid] <= t) lo = mid + 1; else hi = mid;
            }
            int idx = lo < 511 ? lo : 511;
            const float4* src = (const float4*)(x + ((size_t)b * SS + idx) * CC);
            float4*       dst = (float4*)(out + ((size_t)b * LLR + t) * CC);
#pragma unroll
            for (int i = 0; i < 4; i++)
                dst[lane + i * 32] = valid ? src[lane + i * 32] : z;
        }
        return;
    }

    // ================= GEMM slice =================
    uint32_t sb = smem_u32(smem);
    const int wid  = tid >> 5;
    const int lane = tid & 31;

    const int p0  = blockIdx.x * 128;
    const int co0 = blockIdx.y * 128;
    const int batch_base = p0 & ~511;
    const int srow0      = p0 & 511;

    const __half* Ain = layer ? g_Hh : g_Xh;
    const __half* Win = layer ? g_W2h : g_W1h;

    // ---- precomputed load slots (8 cp.async per thread per chunk) ----
    const __half* aptr0[4]; uint32_t adst[4]; int arow[4];
#pragma unroll
    for (int it = 0; it < 4; it++) {
        int u = tid + it * 256;
        int row = u >> 3;
        int cu  = u & 7;
        arow[it] = srow0 + row - 1;
        aptr0[it] = Ain + (size_t)batch_base * CC + (ptrdiff_t)arow[it] * CC + cu * 8;
        adst[it]  = ST_AH + SWZ(row * 128 + cu * 16);
    }
    const __half* wptr0[4]; uint32_t wdst[4];
#pragma unroll
    for (int it = 0; it < 4; it++) {
        int u = tid + it * 256;
        int row = u >> 3;
        int cu  = u & 7;
        wptr0[it] = Win + (size_t)(co0 + row) * 1536 + cu * 8;
        wdst[it]  = ST_WH + SWZ(row * 128 + cu * 16);
    }

#define LOAD_CHUNK(c_, stagebase_) do {                                      \
    const int shift_ = (c_) >> 3;                                            \
    const int koff_  = shift_ * 512 + ((c_) & 7) * 64;                       \
    _Pragma("unroll")                                                        \
    for (int it = 0; it < 4; it++) {                                         \
        bool v_ = (unsigned)(arow[it] + shift_) < 512u;                      \
        cpa16((stagebase_) + adst[it], v_ ? (aptr0[it] + koff_) : Ain,       \
              v_ ? 16 : 0);                                                  \
    }                                                                        \
    _Pragma("unroll")                                                        \
    for (int it = 0; it < 4; it++)                                           \
        cpa16((stagebase_) + wdst[it], wptr0[it] + koff_, 16);               \
    CP_COMMIT();                                                             \
} while (0)

    float acc[2][8][4];
#pragma unroll
    for (int i = 0; i < 2; i++)
#pragma unroll
        for (int j = 0; j < 8; j++)
#pragma unroll
            for (int k = 0; k < 4; k++) acc[i][j][k] = 0.f;

    LOAD_CHUNK(0, sb);
    LOAD_CHUNK(1, sb + STAGE_BYTES);

    const int m0w  = (wid & 3) * 32;
    const int n0w  = (wid >> 2) * 64;
    const int lrow = lane & 15;
    const int lub  = (lane >> 4) * 16;
    uint32_t aoff[2], xrA[2];
#pragma unroll
    for (int mt = 0; mt < 2; mt++) {
        int row = m0w + mt * 16 + lrow;
        aoff[mt] = ST_AH + row * 128;
        xrA[mt]  = (row & 7) << 4;
    }
    uint32_t boff[4], xrB[4];
#pragma unroll
    for (int np = 0; np < 4; np++) {
        int row = n0w + np * 16 + lrow;
        boff[np] = ST_WH + row * 128;
        xrB[np]  = (row & 7) << 4;
    }

#pragma unroll 1
    for (int c = 0; c < NCHUNK; c++) {
        uint32_t stage = sb + (uint32_t)(c & 1) * STAGE_BYTES;
        if (c + 1 < NCHUNK) { CP_WAIT1(); } else { CP_WAIT0(); }
        __syncthreads();

#pragma unroll
        for (int ks = 0; ks < 4; ks++) {
            const uint32_t kb = (uint32_t)(ks * 32) + lub;

            uint32_t af[2][4], bf[4][4];
#pragma unroll
            for (int mt = 0; mt < 2; mt++)
                ldsm4(af[mt][0], af[mt][1], af[mt][2], af[mt][3],
                      stage + aoff[mt] + (kb ^ xrA[mt]));
#pragma unroll
            for (int np = 0; np < 4; np++)
                ldsm4(bf[np][0], bf[np][1], bf[np][2], bf[np][3],
                      stage + boff[np] + (kb ^ xrB[np]));

#pragma unroll
            for (int mt = 0; mt < 2; mt++)
#pragma unroll
                for (int np = 0; np < 4; np++) {
                    mma16816(acc[mt][2*np],   af[mt], bf[np][0], bf[np][2]);
                    mma16816(acc[mt][2*np+1], af[mt], bf[np][1], bf[np][3]);
                }
        }
        __syncthreads();
        if (c + 2 < NCHUNK)
            LOAD_CHUNK(c + 2, stage);
    }

    // epilogue -> g_Y fp32
    const int gr = lane >> 2;
    const int gc = (lane & 3) * 2;
#pragma unroll
    for (int mt = 0; mt < 2; mt++) {
        int row = p0 + m0w + mt * 16 + gr;
#pragma unroll
        for (int nt = 0; nt < 8; nt++) {
            int col = co0 + n0w + nt * 8 + gc;
            *(float2*)(g_Y + (size_t)row * CC + col)       = make_float2(acc[mt][nt][0], acc[mt][nt][1]);
            *(float2*)(g_Y + (size_t)(row + 8) * CC + col) = make_float2(acc[mt][nt][2], acc[mt][nt][3]);
        }
    }
}

// ---------------- bias + relu + LayerNorm (+ optional linear head) ----------------
template<int MODE>
__global__ void k_ln(const float* __restrict__ bias, const float* __restrict__ lng,
                     const float* __restrict__ lnb, const float* __restrict__ lw,
                     const float* __restrict__ lbias, float* __restrict__ outp)
{
    __shared__ float s1[4], s2[4], sd[4];
    const int row = blockIdx.x, tid = threadIdx.x;
    const int wid = tid >> 5, lane = tid & 31;

    float4 v  = ((const float4*)(g_Y + (size_t)row * CC))[tid];
    float4 bb = ((const float4*)bias)[tid];
    float e0 = fmaxf(v.x + bb.x, 0.f);
    float e1 = fmaxf(v.y + bb.y, 0.f);
    float e2 = fmaxf(v.z + bb.z, 0.f);
    float e3 = fmaxf(v.w + bb.w, 0.f);

    float s = e0 + e1 + e2 + e3;
    float q = e0*e0 + e1*e1 + e2*e2 + e3*e3;
#pragma unroll
    for (int o = 16; o > 0; o >>= 1) {
        s += __shfl_xor_sync(0xffffffffu, s, o);
        q += __shfl_xor_sync(0xffffffffu, q, o);
    }
    if (lane == 0) { s1[wid] = s; s2[wid] = q; }
    __syncthreads();
    float ts = s1[0] + s1[1] + s1[2] + s1[3];
    float tq = s2[0] + s2[1] + s2[2] + s2[3];
    float mu = ts * (1.f / 512.f);
    float rs = rsqrtf(tq * (1.f / 512.f) - mu * mu + 1e-5f);

    float4 gg = ((const float4*)lng)[tid];
    float4 bn = ((const float4*)lnb)[tid];
    float o0 = (e0 - mu) * rs * gg.x + bn.x;
    float o1 = (e1 - mu) * rs * gg.y + bn.y;
    float o2 = (e2 - mu) * rs * gg.z + bn.z;
    float o3 = (e3 - mu) * rs * gg.w + bn.w;

    if (MODE == 0) {
        __half2 a = __floats2half2_rn(o0, o1);
        __half2 b = __floats2half2_rn(o2, o3);
        uint32_t hw0 = *reinterpret_cast<uint32_t*>(&a);
        uint32_t hw1 = *reinterpret_cast<uint32_t*>(&b);
        ((uint2*)(g_Hh + (size_t)row * CC))[tid] = make_uint2(hw0, hw1);
    } else {
        float4 lv = ((const float4*)lw)[tid];
        float d = o0 * lv.x + o1 * lv.y + o2 * lv.z + o3 * lv.w;
#pragma unroll
        for (int o = 16; o > 0; o >>= 1)
            d += __shfl_xor_sync(0xffffffffu, d, o);
        if (lane == 0) sd[wid] = d;
        __syncthreads();
        if (tid == 0) {
            float* dst = outp ? outp : g_dummy;
            dst[row] = sd[0] + sd[1] + sd[2] + sd[3] + lbias[0];
        }
    }
}

// ---------------------------------------------------------------------------
extern "C" void kernel_launch(void* const* d_in, const int* in_sizes, int n_in,
                              void* d_out, int out_size)
{
    (void)in_sizes; (void)n_in;
    const float* x   = (const float*)d_in[0];
    const int*   dur = (const int*)d_in[6];
    const float* w1  = (const float*)d_in[7];
    const float* b1  = (const float*)d_in[8];
    const float* g1  = (const float*)d_in[9];
    const float* lb1 = (const float*)d_in[10];
    const float* w2  = (const float*)d_in[11];
    const float* b2  = (const float*)d_in[12];
    const float* g2  = (const float*)d_in[13];
    const float* lb2 = (const float*)d_in[14];
    const float* lw  = (const float*)d_in[15];
    const float* lb  = (const float*)d_in[16];
    float* out = (float*)d_out;

    const bool has_ld  = (long long)out_size >= OUT_EXP + OUT_LD;
    const bool has_mel = (long long)out_size >= OUT_EXP + OUT_LD + OUT_MEL;

    cudaFuncSetAttribute(k_mma, cudaFuncAttributeMaxDynamicSharedMemorySize, MMA_SMEM_TOTAL);

    k_prep<<<NXBLK + NWBLK, 256>>>(x, w1, w2);

    // layer-0 GEMM + fused length regulator (y==4 slice) + mel zeroing
    k_mma<<<dim3(128, 5), 256, MMA_SMEM_TOTAL>>>(0, x, dur, out,
                                                 has_mel ? (out + OUT_EXP + OUT_LD) : nullptr);
    k_ln<0><<<NPOS, 128>>>(b1, g1, lb1, nullptr, nullptr, nullptr);

    k_mma<<<dim3(128, 4), 256, MMA_SMEM_TOTAL>>>(1, x, dur, out, nullptr);
    k_ln<1><<<NPOS, 128>>>(b2, g2, lb2, lw, lb, has_ld ? (out + OUT_EXP) : nullptr);
}